// round 5
// baseline (speedup 1.0000x reference)
#include <cuda_runtime.h>
#include <cuda_bf16.h>
#include <math.h>
#include <stdint.h>

#define BATCH   4
#define CH      512
#define HWSZ    4096
#define NGROUPS 32
#define CPG     16
#define GSIZE   (CPG * HWSZ)

// ---------------- scratch (bf16 intermediates) -------------------------------
__device__ __nv_bfloat16 g_wq[CH * CH];
__device__ __nv_bfloat16 g_wk[CH * CH];
__device__ __nv_bfloat16 g_wv[CH * CH];
__device__ __nv_bfloat16 g_ht[(size_t)BATCH * HWSZ * CH];     // h^T [b][hw][c]
__device__ __nv_bfloat16 g_qt[(size_t)BATCH * HWSZ * CH];     // q^T [b][hw][c]
__device__ __nv_bfloat16 g_kt[(size_t)BATCH * HWSZ * CH];     // k^T [b][hw][c]
__device__ __nv_bfloat16 g_v [(size_t)BATCH * CH * HWSZ];     // v   [b][c][hw]
__device__ __nv_bfloat16 g_attn[(size_t)BATCH * HWSZ * HWSZ]; // attn [b][i][j]

// ---------------- weight fp32 -> bf16 ---------------------------------------
__global__ void convw_kernel(const float* __restrict__ qw,
                             const float* __restrict__ kw,
                             const float* __restrict__ vw) {
    const int i = blockIdx.x * blockDim.x + threadIdx.x;
    float4 a;
    a = ((const float4*)qw)[i];
    ((__nv_bfloat162*)g_wq)[2 * i]     = __floats2bfloat162_rn(a.x, a.y);
    ((__nv_bfloat162*)g_wq)[2 * i + 1] = __floats2bfloat162_rn(a.z, a.w);
    a = ((const float4*)kw)[i];
    ((__nv_bfloat162*)g_wk)[2 * i]     = __floats2bfloat162_rn(a.x, a.y);
    ((__nv_bfloat162*)g_wk)[2 * i + 1] = __floats2bfloat162_rn(a.z, a.w);
    a = ((const float4*)vw)[i];
    ((__nv_bfloat162*)g_wv)[2 * i]     = __floats2bfloat162_rn(a.x, a.y);
    ((__nv_bfloat162*)g_wv)[2 * i + 1] = __floats2bfloat162_rn(a.z, a.w);
}

// ---------------- GroupNorm (fp32 stats, writes bf16 h^T) --------------------
__global__ void groupnorm_kernel(const float* __restrict__ x,
                                 const float* __restrict__ gw,
                                 const float* __restrict__ gb) {
    const int bg  = blockIdx.x;
    const int b   = bg / NGROUPS;
    const int grp = bg % NGROUPS;
    const size_t base = ((size_t)b * CH + (size_t)grp * CPG) * HWSZ;
    const float4* xp = (const float4*)(x + base);
    const int n4 = GSIZE / 4;

    float sum = 0.f, sq = 0.f;
    for (int i = threadIdx.x; i < n4; i += blockDim.x) {
        float4 v = xp[i];
        sum += v.x + v.y + v.z + v.w;
        sq  += v.x * v.x + v.y * v.y + v.z * v.z + v.w * v.w;
    }
    __shared__ float sbuf[64];
    #pragma unroll
    for (int o = 16; o; o >>= 1) {
        sum += __shfl_xor_sync(0xffffffffu, sum, o);
        sq  += __shfl_xor_sync(0xffffffffu, sq,  o);
    }
    const int wid = threadIdx.x >> 5, lid = threadIdx.x & 31;
    const int nw  = blockDim.x >> 5;
    if (lid == 0) { sbuf[wid] = sum; sbuf[32 + wid] = sq; }
    __syncthreads();
    if (threadIdx.x < 32) {
        sum = (lid < nw) ? sbuf[lid]      : 0.f;
        sq  = (lid < nw) ? sbuf[32 + lid] : 0.f;
        #pragma unroll
        for (int o = 16; o; o >>= 1) {
            sum += __shfl_xor_sync(0xffffffffu, sum, o);
            sq  += __shfl_xor_sync(0xffffffffu, sq,  o);
        }
        if (lid == 0) { sbuf[0] = sum; sbuf[1] = sq; }
    }
    __syncthreads();
    const float mu   = sbuf[0] * (1.f / GSIZE);
    const float var  = sbuf[1] * (1.f / GSIZE) - mu * mu;
    const float rstd = rsqrtf(var + 1e-6f);

    __shared__ float s_sc[CPG], s_sh[CPG];
    if (threadIdx.x < CPG) {
        const int c = grp * CPG + threadIdx.x;
        const float sc = gw[c] * rstd;
        s_sc[threadIdx.x] = sc;
        s_sh[threadIdx.x] = gb[c] - mu * sc;
    }
    __syncthreads();

    const float* xb = x + base;
    __nv_bfloat16* ho = g_ht + (size_t)b * HWSZ * CH + grp * CPG;
    for (int idx = threadIdx.x; idx < HWSZ * 2; idx += blockDim.x) {
        const int pos = idx >> 1;
        const int jh  = (idx & 1) * 8;
        __nv_bfloat162 r[4];
        #pragma unroll
        for (int r2 = 0; r2 < 4; r2++) {
            const int j = jh + r2 * 2;
            float v0 = xb[(size_t)j       * HWSZ + pos] * s_sc[j]     + s_sh[j];
            float v1 = xb[(size_t)(j + 1) * HWSZ + pos] * s_sc[j + 1] + s_sh[j + 1];
            r[r2] = __floats2bfloat162_rn(v0, v1);
        }
        *(uint4*)(ho + (size_t)pos * CH + jh) = *(uint4*)r;
    }
}

// ---------------- bf16 MMA GEMM:  C[m][n] = alpha*sum_k A[m][k]*B[n][k] ------
// A row-major [M,K], B row-major [N,K], bf16. CTA 128x128, 4 warps (64x64 each),
// BK=32, 3-stage cp.async pipeline, ldmatrix.x4 fragment loads, fp32 accum.
#define BMt     128
#define BNt     128
#define BKt     32
#define NST     3
#define RSTB    80                       // smem row stride bytes (32 bf16 + 8 pad)
#define AREG_B  (BMt * RSTB)             // 10240
#define STAGE_B (2 * AREG_B)             // 20480 (A then B)
#define SMEM_DYN (NST * STAGE_B)         // 61440

static __device__ __forceinline__ void cp16(uint32_t s, const void* g) {
    asm volatile("cp.async.cg.shared.global [%0], [%1], 16;\n" :: "r"(s), "l"(g));
}

template<bool STORET, bool HASBIAS, bool HASRES, bool OUTBF16>
__global__ void __launch_bounds__(128)
bgemm(const __nv_bfloat16* __restrict__ A, const __nv_bfloat16* __restrict__ B,
      void* __restrict__ Cv, int K, int lda, int ldb, int ldc,
      long long strA, long long strB, long long strC, long long strR,
      float alpha, const float* __restrict__ bias,
      const float* __restrict__ resid)
{
    extern __shared__ __align__(16) char smem_raw[];
    const uint32_t smem0 = (uint32_t)__cvta_generic_to_shared(smem_raw);

    const int bz = blockIdx.z;
    A += (size_t)bz * strA;
    B += (size_t)bz * strB;

    const int m0 = blockIdx.y * BMt, n0 = blockIdx.x * BNt;
    const int t = threadIdx.x, lane = t & 31, warp = t >> 5;
    const int wm = (warp & 1) * 64, wn = (warp >> 1) * 64;
    const int g = lane >> 2, q = lane & 3;

    // loader: thread t owns row t of both tiles (4 x 16B chunks each)
    const __nv_bfloat16* Ag = A + (size_t)(m0 + t) * lda;
    const __nv_bfloat16* Bg = B + (size_t)(n0 + t) * ldb;
    const uint32_t sa_st = (uint32_t)t * RSTB;
    const uint32_t sb_st = AREG_B + (uint32_t)t * RSTB;

    // ldmatrix per-thread source offsets
    const int arow  = lane & 15;
    const int akoff = (lane >> 4) * 8;
    const int brow  = (lane & 7) + ((lane >> 4) << 3);
    const int bkoff = ((lane >> 3) & 1) * 8;
    const uint32_t aoff = (uint32_t)((wm + arow) * RSTB + akoff * 2);
    const uint32_t boff = (uint32_t)(AREG_B + (wn + brow) * RSTB + bkoff * 2);

    const int ntiles = K / BKt;

    // prologue: stages 0, 1
    #pragma unroll
    for (int s = 0; s < 2; s++) {
        const uint32_t sb = smem0 + s * STAGE_B;
        const __nv_bfloat16* ar = Ag + s * BKt;
        const __nv_bfloat16* br = Bg + s * BKt;
        #pragma unroll
        for (int c = 0; c < 4; c++) cp16(sb + sa_st + c * 16, ar + c * 8);
        #pragma unroll
        for (int c = 0; c < 4; c++) cp16(sb + sb_st + c * 16, br + c * 8);
        asm volatile("cp.async.commit_group;\n");
    }

    float acc[4][8][4];
    #pragma unroll
    for (int mt = 0; mt < 4; mt++)
        #pragma unroll
        for (int nt = 0; nt < 8; nt++)
            #pragma unroll
            for (int r = 0; r < 4; r++) acc[mt][nt][r] = 0.f;

    for (int kt = 0; kt < ntiles; kt++) {
        asm volatile("cp.async.wait_group 1;\n");
        __syncthreads();

        if (kt + 2 < ntiles) {
            const uint32_t sb = smem0 + ((kt + 2) % NST) * STAGE_B;
            const __nv_bfloat16* ar = Ag + (size_t)(kt + 2) * BKt;
            const __nv_bfloat16* br = Bg + (size_t)(kt + 2) * BKt;
            #pragma unroll
            for (int c = 0; c < 4; c++) cp16(sb + sa_st + c * 16, ar + c * 8);
            #pragma unroll
            for (int c = 0; c < 4; c++) cp16(sb + sb_st + c * 16, br + c * 8);
        }
        asm volatile("cp.async.commit_group;\n");

        const uint32_t st = smem0 + (kt % NST) * STAGE_B;
        #pragma unroll
        for (int kk = 0; kk < 2; kk++) {
            uint32_t af[4][4], bf[8][2];
            #pragma unroll
            for (int mt = 0; mt < 4; mt++) {
                asm volatile(
                    "ldmatrix.sync.aligned.m8n8.x4.shared.b16 {%0,%1,%2,%3}, [%4];"
                    : "=r"(af[mt][0]), "=r"(af[mt][1]),
                      "=r"(af[mt][2]), "=r"(af[mt][3])
                    : "r"(st + aoff + mt * (16 * RSTB) + kk * 32));
            }
            #pragma unroll
            for (int np = 0; np < 4; np++) {
                asm volatile(
                    "ldmatrix.sync.aligned.m8n8.x4.shared.b16 {%0,%1,%2,%3}, [%4];"
                    : "=r"(bf[2 * np][0]), "=r"(bf[2 * np][1]),
                      "=r"(bf[2 * np + 1][0]), "=r"(bf[2 * np + 1][1])
                    : "r"(st + boff + np * (16 * RSTB) + kk * 32));
            }
            #pragma unroll
            for (int mt = 0; mt < 4; mt++)
                #pragma unroll
                for (int nt = 0; nt < 8; nt++) {
                    asm volatile(
                        "mma.sync.aligned.m16n8k16.row.col.f32.bf16.bf16.f32 "
                        "{%0,%1,%2,%3}, {%4,%5,%6,%7}, {%8,%9}, {%0,%1,%2,%3};"
                        : "+f"(acc[mt][nt][0]), "+f"(acc[mt][nt][1]),
                          "+f"(acc[mt][nt][2]), "+f"(acc[mt][nt][3])
                        : "r"(af[mt][0]), "r"(af[mt][1]),
                          "r"(af[mt][2]), "r"(af[mt][3]),
                          "r"(bf[nt][0]), "r"(bf[nt][1]));
                }
        }
    }

    // epilogue: c0:(m,n) c1:(m,n+1) c2:(m+8,n) c3:(m+8,n+1)
    #pragma unroll
    for (int mt = 0; mt < 4; mt++) {
        const int m = m0 + wm + mt * 16 + g;
        const float bv0 = HASBIAS ? bias[m]     : 0.f;
        const float bv1 = HASBIAS ? bias[m + 8] : 0.f;
        #pragma unroll
        for (int nt = 0; nt < 8; nt++) {
            const int n = n0 + wn + nt * 8 + 2 * q;
            float c0 = acc[mt][nt][0] * alpha + bv0;
            float c1 = acc[mt][nt][1] * alpha + bv0;
            float c2 = acc[mt][nt][2] * alpha + bv1;
            float c3 = acc[mt][nt][3] * alpha + bv1;
            if (OUTBF16) {
                __nv_bfloat16* C = (__nv_bfloat16*)Cv + (size_t)bz * strC;
                if (STORET) {
                    C[(size_t)n       * ldc + m]     = __float2bfloat16_rn(c0);
                    C[(size_t)(n + 1) * ldc + m]     = __float2bfloat16_rn(c1);
                    C[(size_t)n       * ldc + m + 8] = __float2bfloat16_rn(c2);
                    C[(size_t)(n + 1) * ldc + m + 8] = __float2bfloat16_rn(c3);
                } else {
                    *(__nv_bfloat162*)&C[(size_t)m       * ldc + n] =
                        __floats2bfloat162_rn(c0, c1);
                    *(__nv_bfloat162*)&C[(size_t)(m + 8) * ldc + n] =
                        __floats2bfloat162_rn(c2, c3);
                }
            } else {
                float* C = (float*)Cv + (size_t)bz * strC;
                if (HASRES) {
                    const float* R = resid + (size_t)bz * strR;
                    c0 += R[(size_t)m       * ldc + n];
                    c1 += R[(size_t)m       * ldc + n + 1];
                    c2 += R[(size_t)(m + 8) * ldc + n];
                    c3 += R[(size_t)(m + 8) * ldc + n + 1];
                }
                *(float2*)&C[(size_t)m       * ldc + n] = make_float2(c0, c1);
                *(float2*)&C[(size_t)(m + 8) * ldc + n] = make_float2(c2, c3);
            }
        }
    }
}

// ---------------- row softmax over bf16 g_attn (fp32 math) -------------------
__global__ void softmax_kernel() {
    const size_t row = blockIdx.x;
    uint4* p = (uint4*)(g_attn + row * HWSZ);
    uint4 u[2];
    float f[16];
    u[0] = p[threadIdx.x];
    u[1] = p[threadIdx.x + 256];
    #pragma unroll
    for (int i = 0; i < 2; i++) {
        const uint32_t* w = (const uint32_t*)&u[i];
        #pragma unroll
        for (int j = 0; j < 4; j++) {
            float2 v = __bfloat1622float2(*(const __nv_bfloat162*)&w[j]);
            f[i * 8 + j * 2]     = v.x;
            f[i * 8 + j * 2 + 1] = v.y;
        }
    }
    float mx = -1e30f;
    #pragma unroll
    for (int i = 0; i < 16; i++) mx = fmaxf(mx, f[i]);
    __shared__ float sb[32];
    #pragma unroll
    for (int o = 16; o; o >>= 1) mx = fmaxf(mx, __shfl_xor_sync(0xffffffffu, mx, o));
    const int wid = threadIdx.x >> 5, lid = threadIdx.x & 31;
    if (lid == 0) sb[wid] = mx;
    __syncthreads();
    if (threadIdx.x < 32) {
        mx = (lid < 8) ? sb[lid] : -1e30f;
        #pragma unroll
        for (int o = 4; o; o >>= 1) mx = fmaxf(mx, __shfl_xor_sync(0xffffffffu, mx, o));
        if (lid == 0) sb[0] = mx;
    }
    __syncthreads();
    mx = sb[0];

    float sum = 0.f;
    #pragma unroll
    for (int i = 0; i < 16; i++) { f[i] = __expf(f[i] - mx); sum += f[i]; }
    __syncthreads();
    #pragma unroll
    for (int o = 16; o; o >>= 1) sum += __shfl_xor_sync(0xffffffffu, sum, o);
    if (lid == 0) sb[wid] = sum;
    __syncthreads();
    if (threadIdx.x < 32) {
        sum = (lid < 8) ? sb[lid] : 0.f;
        #pragma unroll
        for (int o = 4; o; o >>= 1) sum += __shfl_xor_sync(0xffffffffu, sum, o);
        if (lid == 0) sb[0] = sum;
    }
    __syncthreads();
    const float inv = 1.f / sb[0];
    #pragma unroll
    for (int i = 0; i < 2; i++) {
        uint32_t* w = (uint32_t*)&u[i];
        #pragma unroll
        for (int j = 0; j < 4; j++) {
            __nv_bfloat162 b2 = __floats2bfloat162_rn(f[i * 8 + j * 2] * inv,
                                                      f[i * 8 + j * 2 + 1] * inv);
            w[j] = *(uint32_t*)&b2;
        }
    }
    p[threadIdx.x]       = u[0];
    p[threadIdx.x + 256] = u[1];
}

// ---------------- launch ------------------------------------------------------
extern "C" void kernel_launch(void* const* d_in, const int* in_sizes, int n_in,
                              void* d_out, int out_size) {
    const float* x    = (const float*)d_in[0];
    const float* gn_w = (const float*)d_in[1];
    const float* gn_b = (const float*)d_in[2];
    const float* q_w  = (const float*)d_in[3];
    const float* q_b  = (const float*)d_in[4];
    const float* k_w  = (const float*)d_in[5];
    const float* k_b  = (const float*)d_in[6];
    const float* v_w  = (const float*)d_in[7];
    const float* v_b  = (const float*)d_in[8];
    float* out = (float*)d_out;

    void *wqp, *wkp, *wvp, *htp, *qtp, *ktp, *vp, *ap;
    cudaGetSymbolAddress(&wqp, g_wq);
    cudaGetSymbolAddress(&wkp, g_wk);
    cudaGetSymbolAddress(&wvp, g_wv);
    cudaGetSymbolAddress(&htp, g_ht);
    cudaGetSymbolAddress(&qtp, g_qt);
    cudaGetSymbolAddress(&ktp, g_kt);
    cudaGetSymbolAddress(&vp,  g_v);
    cudaGetSymbolAddress(&ap,  g_attn);
    __nv_bfloat16* wq = (__nv_bfloat16*)wqp;
    __nv_bfloat16* wk = (__nv_bfloat16*)wkp;
    __nv_bfloat16* wv = (__nv_bfloat16*)wvp;
    __nv_bfloat16* ht = (__nv_bfloat16*)htp;
    __nv_bfloat16* qt = (__nv_bfloat16*)qtp;
    __nv_bfloat16* kt = (__nv_bfloat16*)ktp;
    __nv_bfloat16* vv = (__nv_bfloat16*)vp;
    __nv_bfloat16* at = (__nv_bfloat16*)ap;

    cudaFuncSetAttribute(bgemm<true,  true,  false, true>,
                         cudaFuncAttributeMaxDynamicSharedMemorySize, SMEM_DYN);
    cudaFuncSetAttribute(bgemm<false, true,  false, true>,
                         cudaFuncAttributeMaxDynamicSharedMemorySize, SMEM_DYN);
    cudaFuncSetAttribute(bgemm<false, false, false, true>,
                         cudaFuncAttributeMaxDynamicSharedMemorySize, SMEM_DYN);
    cudaFuncSetAttribute(bgemm<false, false, true,  false>,
                         cudaFuncAttributeMaxDynamicSharedMemorySize, SMEM_DYN);

    const long long sHC  = (long long)HWSZ * CH;
    const long long sCHW = (long long)CH * HWSZ;
    const long long sAtt = (long long)HWSZ * HWSZ;

    // 0) weights -> bf16
    convw_kernel<<<CH * CH / 4 / 256, 256>>>(q_w, k_w, v_w);

    // 1) GroupNorm: x -> bf16 h^T
    groupnorm_kernel<<<BATCH * NGROUPS, 512>>>(x, gn_w, gn_b);

    // 2) QKV: C[o][hw] = sum_c W[o][c] ht[hw][c]  (M=512, N=4096, K=512)
    dim3 g1(HWSZ / BNt, CH / BMt, BATCH);          // (32, 4, 4)
    bgemm<true,  true,  false, true><<<g1, 128, SMEM_DYN>>>(wq, ht, qt,
        CH, CH, CH, CH, 0, sHC, sHC, 0, 1.f, q_b, nullptr);
    bgemm<true,  true,  false, true><<<g1, 128, SMEM_DYN>>>(wk, ht, kt,
        CH, CH, CH, CH, 0, sHC, sHC, 0, 1.f, k_b, nullptr);
    bgemm<false, true,  false, true><<<g1, 128, SMEM_DYN>>>(wv, ht, vv,
        CH, CH, CH, HWSZ, 0, sHC, sCHW, 0, 1.f, v_b, nullptr);

    // 3) S[i][j] = (1/sqrt(C)) sum_c qt[i][c] kt[j][c]  (M=N=4096, K=512)
    dim3 g2(HWSZ / BNt, HWSZ / BMt, BATCH);        // (32, 32, 4)
    const float alpha = 1.f / sqrtf((float)CH);
    bgemm<false, false, false, true><<<g2, 128, SMEM_DYN>>>(qt, kt, at,
        CH, CH, CH, HWSZ, sHC, sHC, sAtt, 0, alpha, nullptr, nullptr);

    // 4) softmax rows (bf16 in/out, fp32 math)
    softmax_kernel<<<BATCH * HWSZ, 256>>>();

    // 5) out[c][i] = x[c][i] + sum_j v[c][j] attn[i][j]  (M=512, N=4096, K=4096)
    dim3 g3(HWSZ / BNt, CH / BMt, BATCH);          // (32, 4, 4)
    bgemm<false, false, true,  false><<<g3, 128, SMEM_DYN>>>(vv, at, out,
        HWSZ, HWSZ, HWSZ, HWSZ, sCHW, sAtt, sCHW, sCHW, 1.f, nullptr, x);
}

// round 6
// speedup vs baseline: 1.2270x; 1.2270x over previous
#include <cuda_runtime.h>
#include <cuda_bf16.h>
#include <math.h>
#include <stdint.h>

#define BATCH   4
#define CH      512
#define HWSZ    4096
#define NGROUPS 32
#define CPG     16
#define GSIZE   (CPG * HWSZ)
#define SCALE_W 32.0f
#define SCALE_P 1024.0f

// ---------------- scratch ----------------------------------------------------
__device__ uint8_t g_w8q[CH * CH];
__device__ uint8_t g_w8k[CH * CH];
__device__ uint8_t g_w8v[CH * CH];
__device__ uint8_t g_h8[(size_t)BATCH * HWSZ * CH];     // h^T [b][hw][c]  e4m3
__device__ uint8_t g_q8[(size_t)BATCH * HWSZ * CH];     // q^T [b][hw][c]
__device__ uint8_t g_k8[(size_t)BATCH * HWSZ * CH];     // k^T [b][hw][c]
__device__ uint8_t g_v8[(size_t)BATCH * CH * HWSZ];     // v   [b][c][hw]
__device__ __nv_bfloat16 g_attn[(size_t)BATCH * HWSZ * HWSZ]; // S   [b][i][j]
__device__ uint8_t g_p8[(size_t)BATCH * HWSZ * HWSZ];   // P*1024 [b][i][j]

static __device__ __forceinline__ uint16_t pk8(float lo, float hi) {
    uint16_t r;
    asm("cvt.rn.satfinite.e4m3x2.f32 %0, %1, %2;" : "=h"(r) : "f"(hi), "f"(lo));
    return r;
}

// ---------------- weight fp32 -> e4m3 (x32) ----------------------------------
__global__ void convw_kernel(const float* __restrict__ qw,
                             const float* __restrict__ kw,
                             const float* __restrict__ vw) {
    const int i = blockIdx.x * blockDim.x + threadIdx.x;   // float4 index
    float4 a;
    a = ((const float4*)qw)[i];
    ((uint16_t*)g_w8q)[2 * i]     = pk8(a.x * SCALE_W, a.y * SCALE_W);
    ((uint16_t*)g_w8q)[2 * i + 1] = pk8(a.z * SCALE_W, a.w * SCALE_W);
    a = ((const float4*)kw)[i];
    ((uint16_t*)g_w8k)[2 * i]     = pk8(a.x * SCALE_W, a.y * SCALE_W);
    ((uint16_t*)g_w8k)[2 * i + 1] = pk8(a.z * SCALE_W, a.w * SCALE_W);
    a = ((const float4*)vw)[i];
    ((uint16_t*)g_w8v)[2 * i]     = pk8(a.x * SCALE_W, a.y * SCALE_W);
    ((uint16_t*)g_w8v)[2 * i + 1] = pk8(a.z * SCALE_W, a.w * SCALE_W);
}

// ---------------- GroupNorm (fp32 stats, writes e4m3 h^T) --------------------
__global__ void groupnorm_kernel(const float* __restrict__ x,
                                 const float* __restrict__ gw,
                                 const float* __restrict__ gb) {
    const int bg  = blockIdx.x;
    const int b   = bg / NGROUPS;
    const int grp = bg % NGROUPS;
    const size_t base = ((size_t)b * CH + (size_t)grp * CPG) * HWSZ;
    const float4* xp = (const float4*)(x + base);
    const int n4 = GSIZE / 4;

    float sum = 0.f, sq = 0.f;
    for (int i = threadIdx.x; i < n4; i += blockDim.x) {
        float4 v = xp[i];
        sum += v.x + v.y + v.z + v.w;
        sq  += v.x * v.x + v.y * v.y + v.z * v.z + v.w * v.w;
    }
    __shared__ float sbuf[64];
    #pragma unroll
    for (int o = 16; o; o >>= 1) {
        sum += __shfl_xor_sync(0xffffffffu, sum, o);
        sq  += __shfl_xor_sync(0xffffffffu, sq,  o);
    }
    const int wid = threadIdx.x >> 5, lid = threadIdx.x & 31;
    const int nw  = blockDim.x >> 5;
    if (lid == 0) { sbuf[wid] = sum; sbuf[32 + wid] = sq; }
    __syncthreads();
    if (threadIdx.x < 32) {
        sum = (lid < nw) ? sbuf[lid]      : 0.f;
        sq  = (lid < nw) ? sbuf[32 + lid] : 0.f;
        #pragma unroll
        for (int o = 16; o; o >>= 1) {
            sum += __shfl_xor_sync(0xffffffffu, sum, o);
            sq  += __shfl_xor_sync(0xffffffffu, sq,  o);
        }
        if (lid == 0) { sbuf[0] = sum; sbuf[1] = sq; }
    }
    __syncthreads();
    const float mu   = sbuf[0] * (1.f / GSIZE);
    const float var  = sbuf[1] * (1.f / GSIZE) - mu * mu;
    const float rstd = rsqrtf(var + 1e-6f);

    __shared__ float s_sc[CPG], s_sh[CPG];
    if (threadIdx.x < CPG) {
        const int c = grp * CPG + threadIdx.x;
        const float sc = gw[c] * rstd;
        s_sc[threadIdx.x] = sc;
        s_sh[threadIdx.x] = gb[c] - mu * sc;
    }
    __syncthreads();

    const float* xb = x + base;
    uint8_t* ho = g_h8 + (size_t)b * HWSZ * CH + grp * CPG;
    for (int pos = threadIdx.x; pos < HWSZ; pos += blockDim.x) {
        uint16_t pk[8];
        #pragma unroll
        for (int r2 = 0; r2 < 8; r2++) {
            const int j = r2 * 2;
            float v0 = xb[(size_t)j       * HWSZ + pos] * s_sc[j]     + s_sh[j];
            float v1 = xb[(size_t)(j + 1) * HWSZ + pos] * s_sc[j + 1] + s_sh[j + 1];
            pk[r2] = pk8(v0, v1);
        }
        *(uint4*)(ho + (size_t)pos * CH) = *(uint4*)pk;
    }
}

// ---------------- FP8 MMA GEMM:  C[m][n] = alpha*sum_k A[m][k]*B[n][k] -------
// A: [M,K] e4m3 (lda bytes), B: [N,K] e4m3 (ldb bytes).
// CTA 128x128, 256 threads, 8 warps (64x32 each), BK=64 bytes,
// 3-stage cp.async, ldmatrix.x4 (b16 view), m16n8k32 e4m3, fp32 accum.
// OUT: 0 = e4m3 transposed C[n][m]; 1 = e4m3 C[m][n] (paired);
//      2 = bf16 C[m][n]; 3 = fp32 C[m][n] + resid.
#define BMt     128
#define BNt     128
#define BKt     64
#define NST     3
#define RSTB    80                       // row stride bytes (64 data + 16 pad)
#define AREG_B  (BMt * RSTB)             // 10240
#define STAGE_B (2 * AREG_B)             // 20480
#define SMEM_DYN (NST * STAGE_B)         // 61440

static __device__ __forceinline__ void cp16(uint32_t s, const void* g) {
    asm volatile("cp.async.cg.shared.global [%0], [%1], 16;\n" :: "r"(s), "l"(g));
}

template<int OUT, bool HASBIAS>
__global__ void __launch_bounds__(256, 2)
f8gemm(const uint8_t* __restrict__ A, const uint8_t* __restrict__ B,
       void* __restrict__ Cv, int K, int lda, int ldb, int ldc,
       long long strA, long long strB, long long strC, long long strR,
       float alpha, const float* __restrict__ bias,
       const float* __restrict__ resid)
{
    extern __shared__ __align__(16) char smem_raw[];
    const uint32_t smem0 = (uint32_t)__cvta_generic_to_shared(smem_raw);

    const int bz = blockIdx.z;
    A += (size_t)bz * strA;
    B += (size_t)bz * strB;

    const int m0 = blockIdx.y * BMt, n0 = blockIdx.x * BNt;
    const int t = threadIdx.x, lane = t & 31, warp = t >> 5;
    const int wm = (warp & 1) * 64, wn = (warp >> 1) * 32;
    const int g = lane >> 2, q = lane & 3;

    // loader: thread -> row (t&127), 32B half (t>>7); 2x cp16 each for A and B
    const int lrow = t & 127, lhalf = t >> 7;
    const uint8_t* Ag = A + (size_t)(m0 + lrow) * lda + lhalf * 32;
    const uint8_t* Bg = B + (size_t)(n0 + lrow) * ldb + lhalf * 32;
    const uint32_t sa_st = (uint32_t)(lrow * RSTB + lhalf * 32);
    const uint32_t sb_st = AREG_B + sa_st;

    // ldmatrix addresses (b16 view of fp8 rows)
    const uint32_t aoff = (uint32_t)((wm + (lane & 15)) * RSTB + (lane >> 4) * 16);
    const uint32_t boff = AREG_B +
        (uint32_t)((wn + (lane & 15)) * RSTB + (lane >> 4) * 16);

    const int ntiles = K / BKt;

    #pragma unroll
    for (int s = 0; s < 2; s++) {
        const uint32_t sb = smem0 + s * STAGE_B;
        cp16(sb + sa_st,      Ag + s * BKt);
        cp16(sb + sa_st + 16, Ag + s * BKt + 16);
        cp16(sb + sb_st,      Bg + s * BKt);
        cp16(sb + sb_st + 16, Bg + s * BKt + 16);
        asm volatile("cp.async.commit_group;\n");
    }

    float acc[4][4][4];
    #pragma unroll
    for (int mt = 0; mt < 4; mt++)
        #pragma unroll
        for (int nt = 0; nt < 4; nt++)
            #pragma unroll
            for (int r = 0; r < 4; r++) acc[mt][nt][r] = 0.f;

    for (int kt = 0; kt < ntiles; kt++) {
        asm volatile("cp.async.wait_group 1;\n");
        __syncthreads();

        if (kt + 2 < ntiles) {
            const uint32_t sb = smem0 + ((kt + 2) % NST) * STAGE_B;
            const uint8_t* ar = Ag + (size_t)(kt + 2) * BKt;
            const uint8_t* br = Bg + (size_t)(kt + 2) * BKt;
            cp16(sb + sa_st,      ar);
            cp16(sb + sa_st + 16, ar + 16);
            cp16(sb + sb_st,      br);
            cp16(sb + sb_st + 16, br + 16);
        }
        asm volatile("cp.async.commit_group;\n");

        const uint32_t st = smem0 + (kt % NST) * STAGE_B;
        #pragma unroll
        for (int kk = 0; kk < 2; kk++) {
            uint32_t af[4][4], bf[4][2];
            #pragma unroll
            for (int mt = 0; mt < 4; mt++) {
                asm volatile(
                    "ldmatrix.sync.aligned.m8n8.x4.shared.b16 {%0,%1,%2,%3}, [%4];"
                    : "=r"(af[mt][0]), "=r"(af[mt][1]),
                      "=r"(af[mt][2]), "=r"(af[mt][3])
                    : "r"(st + aoff + mt * (16 * RSTB) + kk * 32));
            }
            #pragma unroll
            for (int np = 0; np < 2; np++) {
                asm volatile(
                    "ldmatrix.sync.aligned.m8n8.x4.shared.b16 {%0,%1,%2,%3}, [%4];"
                    : "=r"(bf[2 * np][0]), "=r"(bf[2 * np + 1][0]),
                      "=r"(bf[2 * np][1]), "=r"(bf[2 * np + 1][1])
                    : "r"(st + boff + np * (16 * RSTB) + kk * 32));
            }
            #pragma unroll
            for (int mt = 0; mt < 4; mt++)
                #pragma unroll
                for (int nt = 0; nt < 4; nt++) {
                    asm volatile(
                        "mma.sync.aligned.m16n8k32.row.col.f32.e4m3.e4m3.f32 "
                        "{%0,%1,%2,%3}, {%4,%5,%6,%7}, {%8,%9}, {%0,%1,%2,%3};"
                        : "+f"(acc[mt][nt][0]), "+f"(acc[mt][nt][1]),
                          "+f"(acc[mt][nt][2]), "+f"(acc[mt][nt][3])
                        : "r"(af[mt][0]), "r"(af[mt][1]),
                          "r"(af[mt][2]), "r"(af[mt][3]),
                          "r"(bf[nt][0]), "r"(bf[nt][1]));
                }
        }
    }

    // epilogue: c0:(m,n) c1:(m,n+1) c2:(m+8,n) c3:(m+8,n+1)
    #pragma unroll
    for (int mt = 0; mt < 4; mt++) {
        const int m = m0 + wm + mt * 16 + g;
        const float bv0 = HASBIAS ? bias[m]     : 0.f;
        const float bv1 = HASBIAS ? bias[m + 8] : 0.f;
        #pragma unroll
        for (int nt = 0; nt < 4; nt++) {
            const int n = n0 + wn + nt * 8 + 2 * q;
            float c0 = acc[mt][nt][0] * alpha + bv0;
            float c1 = acc[mt][nt][1] * alpha + bv0;
            float c2 = acc[mt][nt][2] * alpha + bv1;
            float c3 = acc[mt][nt][3] * alpha + bv1;
            if (OUT == 0) {               // e4m3, transposed C[n][m]
                uint8_t* C = (uint8_t*)Cv + (size_t)bz * strC;
                C[(size_t)n       * ldc + m]     = (uint8_t)(pk8(c0, 0.f) & 0xff);
                C[(size_t)(n + 1) * ldc + m]     = (uint8_t)(pk8(c1, 0.f) & 0xff);
                C[(size_t)n       * ldc + m + 8] = (uint8_t)(pk8(c2, 0.f) & 0xff);
                C[(size_t)(n + 1) * ldc + m + 8] = (uint8_t)(pk8(c3, 0.f) & 0xff);
            } else if (OUT == 1) {        // e4m3, natural C[m][n]
                uint8_t* C = (uint8_t*)Cv + (size_t)bz * strC;
                *(uint16_t*)&C[(size_t)m       * ldc + n] = pk8(c0, c1);
                *(uint16_t*)&C[(size_t)(m + 8) * ldc + n] = pk8(c2, c3);
            } else if (OUT == 2) {        // bf16 natural
                __nv_bfloat16* C = (__nv_bfloat16*)Cv + (size_t)bz * strC;
                *(__nv_bfloat162*)&C[(size_t)m       * ldc + n] =
                    __floats2bfloat162_rn(c0, c1);
                *(__nv_bfloat162*)&C[(size_t)(m + 8) * ldc + n] =
                    __floats2bfloat162_rn(c2, c3);
            } else {                      // fp32 + residual
                float* C = (float*)Cv + (size_t)bz * strC;
                const float* R = resid + (size_t)bz * strR;
                c0 += R[(size_t)m       * ldc + n];
                c1 += R[(size_t)m       * ldc + n + 1];
                c2 += R[(size_t)(m + 8) * ldc + n];
                c3 += R[(size_t)(m + 8) * ldc + n + 1];
                *(float2*)&C[(size_t)m       * ldc + n] = make_float2(c0, c1);
                *(float2*)&C[(size_t)(m + 8) * ldc + n] = make_float2(c2, c3);
            }
        }
    }
}

// ---------------- softmax: bf16 S rows -> e4m3 P*1024 ------------------------
__global__ void softmax_kernel() {
    const size_t row = blockIdx.x;
    const uint4* p = (const uint4*)(g_attn + row * HWSZ);
    uint4 u[2];
    float f[16];
    u[0] = p[threadIdx.x];
    u[1] = p[threadIdx.x + 256];
    #pragma unroll
    for (int i = 0; i < 2; i++) {
        const uint32_t* w = (const uint32_t*)&u[i];
        #pragma unroll
        for (int j = 0; j < 4; j++) {
            float2 v = __bfloat1622float2(*(const __nv_bfloat162*)&w[j]);
            f[i * 8 + j * 2]     = v.x;
            f[i * 8 + j * 2 + 1] = v.y;
        }
    }
    float mx = -1e30f;
    #pragma unroll
    for (int i = 0; i < 16; i++) mx = fmaxf(mx, f[i]);
    __shared__ float sb[32];
    #pragma unroll
    for (int o = 16; o; o >>= 1) mx = fmaxf(mx, __shfl_xor_sync(0xffffffffu, mx, o));
    const int wid = threadIdx.x >> 5, lid = threadIdx.x & 31;
    if (lid == 0) sb[wid] = mx;
    __syncthreads();
    if (threadIdx.x < 32) {
        mx = (lid < 8) ? sb[lid] : -1e30f;
        #pragma unroll
        for (int o = 4; o; o >>= 1) mx = fmaxf(mx, __shfl_xor_sync(0xffffffffu, mx, o));
        if (lid == 0) sb[0] = mx;
    }
    __syncthreads();
    mx = sb[0];

    float sum = 0.f;
    #pragma unroll
    for (int i = 0; i < 16; i++) { f[i] = __expf(f[i] - mx); sum += f[i]; }
    __syncthreads();
    #pragma unroll
    for (int o = 16; o; o >>= 1) sum += __shfl_xor_sync(0xffffffffu, sum, o);
    if (lid == 0) sb[wid] = sum;
    __syncthreads();
    if (threadIdx.x < 32) {
        sum = (lid < 8) ? sb[lid] : 0.f;
        #pragma unroll
        for (int o = 4; o; o >>= 1) sum += __shfl_xor_sync(0xffffffffu, sum, o);
        if (lid == 0) sb[0] = sum;
    }
    __syncthreads();
    const float inv = SCALE_P / sb[0];

    uint2* po = (uint2*)(g_p8 + row * HWSZ);
    #pragma unroll
    for (int i = 0; i < 2; i++) {
        uint16_t pk[4];
        #pragma unroll
        for (int j = 0; j < 4; j++)
            pk[j] = pk8(f[i * 8 + j * 2] * inv, f[i * 8 + j * 2 + 1] * inv);
        po[threadIdx.x + i * 256] = *(uint2*)pk;
    }
}

// ---------------- launch ------------------------------------------------------
extern "C" void kernel_launch(void* const* d_in, const int* in_sizes, int n_in,
                              void* d_out, int out_size) {
    const float* x    = (const float*)d_in[0];
    const float* gn_w = (const float*)d_in[1];
    const float* gn_b = (const float*)d_in[2];
    const float* q_w  = (const float*)d_in[3];
    const float* q_b  = (const float*)d_in[4];
    const float* k_w  = (const float*)d_in[5];
    const float* k_b  = (const float*)d_in[6];
    const float* v_w  = (const float*)d_in[7];
    const float* v_b  = (const float*)d_in[8];
    float* out = (float*)d_out;

    void *wqp, *wkp, *wvp, *hp, *qp, *kp, *vp, *ap, *pp;
    cudaGetSymbolAddress(&wqp, g_w8q);
    cudaGetSymbolAddress(&wkp, g_w8k);
    cudaGetSymbolAddress(&wvp, g_w8v);
    cudaGetSymbolAddress(&hp,  g_h8);
    cudaGetSymbolAddress(&qp,  g_q8);
    cudaGetSymbolAddress(&kp,  g_k8);
    cudaGetSymbolAddress(&vp,  g_v8);
    cudaGetSymbolAddress(&ap,  g_attn);
    cudaGetSymbolAddress(&pp,  g_p8);
    uint8_t* wq = (uint8_t*)wqp;
    uint8_t* wk = (uint8_t*)wkp;
    uint8_t* wv = (uint8_t*)wvp;
    uint8_t* h8 = (uint8_t*)hp;
    uint8_t* q8 = (uint8_t*)qp;
    uint8_t* k8 = (uint8_t*)kp;
    uint8_t* v8 = (uint8_t*)vp;
    __nv_bfloat16* at = (__nv_bfloat16*)ap;
    uint8_t* p8 = (uint8_t*)pp;

    cudaFuncSetAttribute(f8gemm<0, true>,
                         cudaFuncAttributeMaxDynamicSharedMemorySize, SMEM_DYN);
    cudaFuncSetAttribute(f8gemm<1, true>,
                         cudaFuncAttributeMaxDynamicSharedMemorySize, SMEM_DYN);
    cudaFuncSetAttribute(f8gemm<2, false>,
                         cudaFuncAttributeMaxDynamicSharedMemorySize, SMEM_DYN);
    cudaFuncSetAttribute(f8gemm<3, false>,
                         cudaFuncAttributeMaxDynamicSharedMemorySize, SMEM_DYN);

    const long long sHC  = (long long)HWSZ * CH;
    const long long sCHW = (long long)CH * HWSZ;
    const long long sAtt = (long long)HWSZ * HWSZ;

    // 0) weights -> e4m3 (x32)
    convw_kernel<<<CH * CH / 4 / 256, 256>>>(q_w, k_w, v_w);

    // 1) GroupNorm: x -> e4m3 h^T
    groupnorm_kernel<<<BATCH * NGROUPS, 512>>>(x, gn_w, gn_b);

    // 2) QKV: acc = sum_c (32W)[o][c] h[hw][c]; alpha=1/32, +bias
    dim3 g1(HWSZ / BNt, CH / BMt, BATCH);          // (32, 4, 4)
    f8gemm<0, true><<<g1, 256, SMEM_DYN>>>(wq, h8, q8, CH, CH, CH, CH,
        0, sHC, sHC, 0, 1.f / SCALE_W, q_b, nullptr);
    f8gemm<0, true><<<g1, 256, SMEM_DYN>>>(wk, h8, k8, CH, CH, CH, CH,
        0, sHC, sHC, 0, 1.f / SCALE_W, k_b, nullptr);
    f8gemm<1, true><<<g1, 256, SMEM_DYN>>>(wv, h8, v8, CH, CH, CH, HWSZ,
        0, sHC, sCHW, 0, 1.f / SCALE_W, v_b, nullptr);

    // 3) S[i][j] = (1/sqrt(C)) sum_c q[i][c] k[j][c]  -> bf16
    dim3 g2(HWSZ / BNt, HWSZ / BMt, BATCH);        // (32, 32, 4)
    const float alpha = 1.f / sqrtf((float)CH);
    f8gemm<2, false><<<g2, 256, SMEM_DYN>>>(q8, k8, at, CH, CH, CH, HWSZ,
        sHC, sHC, sAtt, 0, alpha, nullptr, nullptr);

    // 4) softmax rows -> e4m3 P*1024
    softmax_kernel<<<BATCH * HWSZ, 256>>>();

    // 5) out[c][i] = x[c][i] + (1/1024) sum_j v[c][j] P1024[i][j]
    dim3 g3(HWSZ / BNt, CH / BMt, BATCH);          // (32, 4, 4)
    f8gemm<3, false><<<g3, 256, SMEM_DYN>>>(v8, p8, out, HWSZ, HWSZ, HWSZ, HWSZ,
        sCHW, sAtt, sCHW, sCHW, 1.f / SCALE_P, nullptr, x);
}